// round 9
// baseline (speedup 1.0000x reference)
#include <cuda_runtime.h>
#include <cstdint>

#define BB   256   // batch
#define TT   512   // time steps
#define II   64    // input dim
#define HH   256   // hidden dim
#define NCTA 128   // persistent grid size (8 batch tiles x 16 hidden tiles)
#define TPB  256

// ---------------- global scratch (static device arrays; no allocations) ----
__device__ float    g_h1[(size_t)BB * TT * HH];   // layer-0 outputs (128MB)
__device__ float    g_h[2][BB * HH];              // double-buffered hidden state
__device__ float    g_last[BB * HH];              // final h2 (t = T-1)
__device__ unsigned g_arrived;
__device__ unsigned g_release;

__global__ void init_sync_kernel() { g_arrived = 0u; g_release = 0u; }

// ---------------- helpers ---------------------------------------------------
__device__ __forceinline__ unsigned long long pack2(float x) {
    unsigned long long r;
    asm("mov.b64 %0, {%1, %1};" : "=l"(r) : "f"(x));
    return r;
}
__device__ __forceinline__ void fma2(unsigned long long& acc,
                                     unsigned long long a, unsigned long long b) {
    // Blackwell packed fp32x2 FMA: 2 FMAs/instr, exact fp32 numerics.
    asm("fma.rn.f32x2 %0, %1, %2, %0;" : "+l"(acc) : "l"(a), "l"(b));
}
__device__ __forceinline__ float sigmoidf_(float x) {
    return 1.0f / (1.0f + __expf(-x));
}
__device__ __forceinline__ float tanhf_(float x) {
    // robust: large +x -> 1, large -x -> -1, no NaN
    return 1.0f - 2.0f / (__expf(2.0f * x) + 1.0f);
}

__device__ __forceinline__ void grid_barrier(unsigned want) {
    __syncthreads();
    if (threadIdx.x == 0) {
        __threadfence();  // publish our h writes before arriving
        unsigned arrived = atomicAdd(&g_arrived, 1u) + 1u;
        if (arrived == want * NCTA) {
            atomicExch(&g_release, want);
        } else {
            while (*(volatile unsigned*)&g_release < want) __nanosleep(64);
        }
        __threadfence();  // acquire
    }
    __syncthreads();
}

// ---------------- persistent 2-layer LSTM ----------------------------------
// SMEM layout (floats):
//   Ws    [512][64]  k-major weight slice (input rows then recurrent rows)
//   Is    [512][32]  k-major step input [x_t | h_{t-1}] for this batch tile
//   gates [2][64][32] split-K partial gate pre-activations
//   c_s   [16][32]   cell state for (hidden-slice x batch-tile)
//   bias  [64]
#define SM_WS    (512 * 64)
#define SM_IS    (512 * 32)
#define SM_GATES (2 * 64 * 32)
#define SM_CS    (16 * 32)
#define SM_BIAS  64
#define SMEM_FLOATS (SM_WS + SM_IS + SM_GATES + SM_CS + SM_BIAS)
#define SMEM_BYTES  (SMEM_FLOATS * 4)

__global__ void __launch_bounds__(TPB, 1)
lstm_persistent_kernel(const float* __restrict__ x,
                       const float* __restrict__ Wih0, const float* __restrict__ Whh0,
                       const float* __restrict__ bih0, const float* __restrict__ bhh0,
                       const float* __restrict__ Wih1, const float* __restrict__ Whh1,
                       const float* __restrict__ bih1, const float* __restrict__ bhh1)
{
    extern __shared__ float smem[];
    float* Ws     = smem;
    float* Is     = Ws + SM_WS;
    float* gates  = Is + SM_IS;
    float* c_s    = gates + SM_GATES;
    float* bias_s = c_s + SM_CS;

    const int tid = threadIdx.x;
    const int bt  = blockIdx.x & 7;    // 8 batch tiles of 32
    const int ht  = blockIdx.x >> 3;   // 16 hidden tiles of 16 units
    const int b0  = bt * 32;
    const int hu0 = ht * 16;

    // GEMM thread mapping: split-K halves, 4 gate-rows x 4 batch per thread
    const int kh  = tid >> 7;          // 0..1 (k half)
    const int t7  = tid & 127;
    const int rr0 = (t7 & 15) * 4;     // row quad within 64 CTA gate rows
    const int bq0 = (t7 >> 4) * 4;     // batch quad within 32

    // fill mapping: one batch lane per thread, 8 k-chunks
    const int fb = tid & 31;
    const int fq = tid >> 5;

    unsigned ep = 0;

    for (int l = 0; l < 2; l++) {
        const int Kin = (l == 0) ? II : HH;
        const int K   = Kin + HH;          // 320 or 512
        const int K2  = K >> 1;
        const float* Wih = (l == 0) ? Wih0 : Wih1;
        const float* Whh = (l == 0) ? Whh0 : Whh1;
        const float* bih = (l == 0) ? bih0 : bih1;
        const float* bhh = (l == 0) ? bhh0 : bhh1;

        // ---- load weight slice, k-major: Ws[k][rr], rr = gate*16 + uu ----
        for (int idx = tid; idx < K * 64; idx += TPB) {
            int k = idx >> 6, rr = idx & 63;
            int gate = rr >> 4, uu = rr & 15;
            int grow = gate * HH + hu0 + uu;
            float w = (k < Kin) ? Wih[(size_t)grow * Kin + k]
                                : Whh[(size_t)grow * HH + (k - Kin)];
            Ws[k * 64 + rr] = w;
        }
        if (tid < 64) {
            int gate = tid >> 4, uu = tid & 15;
            int grow = gate * HH + hu0 + uu;
            bias_s[tid] = bih[grow] + bhh[grow];
        }
        // ---- zero c and our h slices in both global buffers ----
        for (int e = tid; e < 512; e += TPB) {
            int uu = e >> 5, bb = e & 31;
            c_s[e] = 0.0f;
            size_t hidx = (size_t)(b0 + bb) * HH + hu0 + uu;
            g_h[0][hidx] = 0.0f;
            g_h[1][hidx] = 0.0f;
        }
        grid_barrier(++ep);

        for (int t = 0; t < TT; t++) {
            const int cur = t & 1;
            const int nxt = cur ^ 1;

            // ---------- fill Is[k][bb] = [ x_t | h_{t-1} ] ----------
            {
                const float* arow = (l == 0)
                    ? (x    + ((size_t)(b0 + fb) * TT + t) * II)
                    : (g_h1 + ((size_t)(b0 + fb) * TT + t) * HH);
                const int nk = Kin >> 3;       // 8 or 32
                const int k0 = fq * nk;
                for (int kk = 0; kk < nk; kk += 4) {
                    float4 v = __ldcg((const float4*)(arow + k0 + kk));
                    Is[(k0 + kk + 0) * 32 + fb] = v.x;
                    Is[(k0 + kk + 1) * 32 + fb] = v.y;
                    Is[(k0 + kk + 2) * 32 + fb] = v.z;
                    Is[(k0 + kk + 3) * 32 + fb] = v.w;
                }
                const float* hrow = g_h[cur] + (size_t)(b0 + fb) * HH;
                const int h0 = fq * 32;
                for (int kk = 0; kk < 32; kk += 4) {
                    float4 v = __ldcg((const float4*)(hrow + h0 + kk));
                    Is[(Kin + h0 + kk + 0) * 32 + fb] = v.x;
                    Is[(Kin + h0 + kk + 1) * 32 + fb] = v.y;
                    Is[(Kin + h0 + kk + 2) * 32 + fb] = v.z;
                    Is[(Kin + h0 + kk + 3) * 32 + fb] = v.w;
                }
            }
            __syncthreads();

            // ---------- GEMM: gates_partial[kh] += Ws^T(slice) . Is ----------
            {
                unsigned long long acc[4][2] = {};
                const int kb = kh * K2;
                const float* wp = Ws + (size_t)kb * 64 + rr0;
                const float* ip = Is + (size_t)kb * 32 + bq0;
                #pragma unroll 4
                for (int k = 0; k < K2; k++) {
                    const float4 w = *(const float4*)(wp);
                    const ulonglong2 vv = *(const ulonglong2*)(ip);
                    #pragma unroll
                    for (int r = 0; r < 4; r++) {
                        unsigned long long wd = pack2(((const float*)&w)[r]);
                        fma2(acc[r][0], wd, vv.x);
                        fma2(acc[r][1], wd, vv.y);
                    }
                    wp += 64;
                    ip += 32;
                }
                #pragma unroll
                for (int r = 0; r < 4; r++) {
                    #pragma unroll
                    for (int p = 0; p < 2; p++) {
                        union { unsigned long long u; float2 f; } cv;
                        cv.u = acc[r][p];
                        gates[(kh * 64 + rr0 + r) * 32 + bq0 + 2 * p + 0] = cv.f.x;
                        gates[(kh * 64 + rr0 + r) * 32 + bq0 + 2 * p + 1] = cv.f.y;
                    }
                }
            }
            __syncthreads();

            // ---------- gate nonlinearities + state update ----------
            #pragma unroll
            for (int j = 0; j < 2; j++) {
                int e  = tid + j * TPB;           // 0..511
                int uu = e >> 5, bb = e & 31;
                float gi = gates[( 0 + uu) * 32 + bb] + gates[(64 +  0 + uu) * 32 + bb] + bias_s[ 0 + uu];
                float gf = gates[(16 + uu) * 32 + bb] + gates[(64 + 16 + uu) * 32 + bb] + bias_s[16 + uu];
                float gg = gates[(32 + uu) * 32 + bb] + gates[(64 + 32 + uu) * 32 + bb] + bias_s[32 + uu];
                float go = gates[(48 + uu) * 32 + bb] + gates[(64 + 48 + uu) * 32 + bb] + bias_s[48 + uu];
                float c  = c_s[e];
                c = sigmoidf_(gf) * c + sigmoidf_(gi) * tanhf_(gg);
                float h = sigmoidf_(go) * tanhf_(c);
                c_s[e] = c;
                size_t hidx = (size_t)(b0 + bb) * HH + hu0 + uu;
                g_h[nxt][hidx] = h;
                if (l == 0) {
                    g_h1[((size_t)(b0 + bb) * TT + t) * HH + hu0 + uu] = h;
                } else if (t == TT - 1) {
                    g_last[hidx] = h;
                }
            }
            grid_barrier(++ep);
        }
    }
}

// ---------------- epilogue: y = (last @ W1^T + b1) @ W2^T + b2 --------------
__global__ void __launch_bounds__(256)
epilogue_kernel(const float* __restrict__ W1, const float* __restrict__ b1,
                const float* __restrict__ W2, const float* __restrict__ b2,
                float* __restrict__ out)
{
    const int b    = blockIdx.x;      // one batch row per block
    const int tid  = threadIdx.x;
    const int lane = tid & 31;
    const int warp = tid >> 5;        // 8 warps

    __shared__ float last_s[HH];
    __shared__ float y_s[5 * HH];     // 1280

    last_s[tid] = g_last[(size_t)b * HH + tid];
    __syncthreads();

    // stage 1: warp-per-row dot products (coalesced W1 reads)
    for (int j = warp; j < 5 * HH; j += 8) {
        const float* wr = W1 + (size_t)j * HH;
        float acc = 0.0f;
        for (int k = lane; k < HH; k += 32) acc += wr[k] * last_s[k];
        #pragma unroll
        for (int o = 16; o; o >>= 1) acc += __shfl_down_sync(0xffffffffu, acc, o);
        if (lane == 0) y_s[j] = acc + b1[j];
    }
    __syncthreads();

    // stage 2: 4 outputs, one per warp
    if (warp < 4) {
        const float* wr = W2 + (size_t)warp * (5 * HH);
        float acc = 0.0f;
        for (int j = lane; j < 5 * HH; j += 32) acc += wr[j] * y_s[j];
        #pragma unroll
        for (int o = 16; o; o >>= 1) acc += __shfl_down_sync(0xffffffffu, acc, o);
        if (lane == 0) out[b * 4 + warp] = acc + b2[warp];
    }
}

// ---------------- launcher ---------------------------------------------------
extern "C" void kernel_launch(void* const* d_in, const int* in_sizes, int n_in,
                              void* d_out, int out_size)
{
    const float* x    = (const float*)d_in[0];
    const float* Wih0 = (const float*)d_in[1];
    const float* Whh0 = (const float*)d_in[2];
    const float* bih0 = (const float*)d_in[3];
    const float* bhh0 = (const float*)d_in[4];
    const float* Wih1 = (const float*)d_in[5];
    const float* Whh1 = (const float*)d_in[6];
    const float* bih1 = (const float*)d_in[7];
    const float* bhh1 = (const float*)d_in[8];
    const float* W1   = (const float*)d_in[9];
    const float* b1   = (const float*)d_in[10];
    const float* W2   = (const float*)d_in[11];
    const float* b2   = (const float*)d_in[12];
    float* out = (float*)d_out;

    cudaFuncSetAttribute(lstm_persistent_kernel,
                         cudaFuncAttributeMaxDynamicSharedMemorySize, SMEM_BYTES);

    init_sync_kernel<<<1, 1>>>();
    lstm_persistent_kernel<<<NCTA, TPB, SMEM_BYTES>>>(
        x, Wih0, Whh0, bih0, bhh0, Wih1, Whh1, bih1, bhh1);
    epilogue_kernel<<<BB, 256>>>(W1, b1, W2, b2, out);
}

// round 10
// speedup vs baseline: 1.3334x; 1.3334x over previous
#include <cuda_runtime.h>
#include <cstdint>

#define BB   256
#define TT   512
#define II   64
#define HH   256
#define G4   1024   // 4*H
#define NCTA 128
#define TPB  256

// ---------------- global scratch (static; no allocations) ------------------
__device__ float    g_xg[(size_t)BB * TT * G4];   // [T][B][4H]  512MB
__device__ float    g_h1[(size_t)BB * TT * HH];   // [B][T][H]   128MB
__device__ float    g_h[2][BB * HH];
__device__ float    g_last[BB * HH];
__device__ unsigned g_arrived;
__device__ unsigned g_release;

__global__ void init_sync_kernel() { g_arrived = 0u; g_release = 0u; }

// ---------------- helpers ---------------------------------------------------
__device__ __forceinline__ unsigned long long pack2(float x) {
    unsigned long long r;
    asm("mov.b64 %0, {%1, %1};" : "=l"(r) : "f"(x));
    return r;
}
__device__ __forceinline__ void fma2(unsigned long long& acc,
                                     unsigned long long a, unsigned long long b) {
    asm("fma.rn.f32x2 %0, %1, %2, %0;" : "+l"(acc) : "l"(a), "l"(b));
}
__device__ __forceinline__ float sigmoidf_(float x) {
    return 1.0f / (1.0f + __expf(-x));
}
__device__ __forceinline__ float tanhf_(float x) {
    return 1.0f - 2.0f / (__expf(2.0f * x) + 1.0f);
}

__device__ __forceinline__ void grid_barrier(unsigned want) {
    __syncthreads();
    if (threadIdx.x == 0) {
        __threadfence();  // publish h writes
        unsigned a = atomicAdd(&g_arrived, 1u) + 1u;
        if (a == want * NCTA) {
            atomicExch(&g_release, want);
        } else {
            while (*((volatile unsigned*)&g_release) < want) {}
        }
        __threadfence();  // acquire
    }
    __syncthreads();
}

// ======================= bulk GEMM: xg = A @ W^T + bias =====================
// A[M=BB*TT][K] row-major (row m = b*T + t), W[G4][K] row-major.
// Output permuted to g_xg[t*BB + b][G4]. 128x128 tile, k-chunk 16,
// 256 threads, 8x8 microtile with fp32x2 FMA.
template<int K, bool A_IS_H1>
__global__ void __launch_bounds__(256, 2)
gemm_xg_kernel(const float* __restrict__ Ain, const float* __restrict__ W,
               const float* __restrict__ bih, const float* __restrict__ bhh)
{
    __shared__ float As[16 * 132];
    __shared__ float Bs[16 * 132];
    const float* A = A_IS_H1 ? g_h1 : Ain;

    const int m0  = (int)(blockIdx.x >> 3) * 128;
    const int n0  = (int)(blockIdx.x & 7) * 128;
    const int tid = threadIdx.x;
    const int tx  = tid & 15;          // N direction
    const int ty  = tid >> 4;          // M direction
    const int lm  = tid >> 2;          // load: row 0..63 (+64 on 2nd pass)
    const int lk  = (tid & 3) * 4;     // load: k sub-offset {0,4,8,12}

    unsigned long long acc[8][4];
    #pragma unroll
    for (int m = 0; m < 8; m++)
        #pragma unroll
        for (int n = 0; n < 4; n++) acc[m][n] = 0ull;

    for (int k0 = 0; k0 < K; k0 += 16) {
        #pragma unroll
        for (int i = 0; i < 2; i++) {
            int m = lm + i * 64;
            float4 va = *(const float4*)(A + (size_t)(m0 + m) * K + k0 + lk);
            float4 vb = *(const float4*)(W + (size_t)(n0 + m) * K + k0 + lk);
            As[(lk + 0) * 132 + m] = va.x;  As[(lk + 1) * 132 + m] = va.y;
            As[(lk + 2) * 132 + m] = va.z;  As[(lk + 3) * 132 + m] = va.w;
            Bs[(lk + 0) * 132 + m] = vb.x;  Bs[(lk + 1) * 132 + m] = vb.y;
            Bs[(lk + 2) * 132 + m] = vb.z;  Bs[(lk + 3) * 132 + m] = vb.w;
        }
        __syncthreads();
        #pragma unroll
        for (int k = 0; k < 16; k++) {
            const float* ar = As + k * 132 + ty * 8;
            const float* br = Bs + k * 132 + tx * 8;
            ulonglong2 b0 = *(const ulonglong2*)(br);
            ulonglong2 b1 = *(const ulonglong2*)(br + 4);
            float4 a0 = *(const float4*)(ar);
            float4 a1 = *(const float4*)(ar + 4);
            float am[8] = {a0.x, a0.y, a0.z, a0.w, a1.x, a1.y, a1.z, a1.w};
            #pragma unroll
            for (int m = 0; m < 8; m++) {
                unsigned long long wd = pack2(am[m]);
                fma2(acc[m][0], wd, b0.x);
                fma2(acc[m][1], wd, b0.y);
                fma2(acc[m][2], wd, b1.x);
                fma2(acc[m][3], wd, b1.y);
            }
        }
        __syncthreads();
    }

    const int col = n0 + tx * 8;
    float bias[8];
    #pragma unroll
    for (int j = 0; j < 8; j++) bias[j] = bih[col + j] + bhh[col + j];

    #pragma unroll
    for (int m = 0; m < 8; m++) {
        int mi   = m0 + ty * 8 + m;                  // = b*T + t
        int orow = (mi & (TT - 1)) * BB + (mi >> 9); // -> t*B + b
        float o[8];
        #pragma unroll
        for (int n = 0; n < 4; n++) {
            union { unsigned long long u; float2 f; } cv; cv.u = acc[m][n];
            o[2 * n]     = cv.f.x + bias[2 * n];
            o[2 * n + 1] = cv.f.y + bias[2 * n + 1];
        }
        float4* dst = (float4*)(g_xg + (size_t)orow * G4 + col);
        dst[0] = make_float4(o[0], o[1], o[2], o[3]);
        dst[1] = make_float4(o[4], o[5], o[6], o[7]);
    }
}

// ======================= persistent recurrent layer =========================
// SMEM (floats):
//   Ws    [256][64]   k-major Whh slice
//   Is    [256][32]   k-major h_{t-1} for the batch tile
//   gates [2][64][33] split-K partials (padded rows -> conflict-free)
//   xg_s  [64][33]    staged xg_t slice (padded)
//   c_s   [16][32]
#define SM_WS    (HH * 64)
#define SM_IS    (HH * 32)
#define SM_GATES (2 * 64 * 33)
#define SM_XG    (64 * 33)
#define SM_CS    (16 * 32)
#define SMEM_FLOATS (SM_WS + SM_IS + SM_GATES + SM_XG + SM_CS)
#define SMEM_BYTES  (SMEM_FLOATS * 4)

__global__ void __launch_bounds__(TPB, 1)
lstm_layer_kernel(const float* __restrict__ Whh, int layer)
{
    extern __shared__ float smem[];
    float* Ws    = smem;
    float* Is    = Ws + SM_WS;
    float* gates = Is + SM_IS;
    float* xg_s  = gates + SM_GATES;
    float* c_s   = xg_s + SM_XG;

    const int tid = threadIdx.x;
    const int bt  = blockIdx.x & 7;    // 8 batch tiles of 32
    const int ht  = blockIdx.x >> 3;   // 16 hidden tiles of 16 units
    const int b0  = bt * 32;
    const int hu0 = ht * 16;

    const int kh  = tid >> 7;          // split-K half
    const int t7  = tid & 127;
    const int rr0 = (t7 & 15) * 4;     // gate-row quad (of 64)
    const int bq0 = (t7 >> 4) * 4;     // batch quad (of 32)

    const int fb = tid & 31;           // fill: batch lane
    const int fq = tid >> 5;           // fill: k chunk

    // ---- weights: Ws[k*64 + rr], rr = gate*16 + uu ----
    for (int idx = tid; idx < HH * 64; idx += TPB) {
        int k = idx >> 6, rr = idx & 63;
        int grow = (rr >> 4) * HH + hu0 + (rr & 15);
        Ws[idx] = Whh[(size_t)grow * HH + k];
    }
    // ---- zero c and our h slices in both buffers ----
    for (int e = tid; e < 512; e += TPB) {
        int uu = e >> 5, bb = e & 31;
        c_s[e] = 0.0f;
        size_t hidx = (size_t)(b0 + bb) * HH + hu0 + uu;
        g_h[0][hidx] = 0.0f;
        g_h[1][hidx] = 0.0f;
    }
    grid_barrier(1);
    unsigned ep = 1;

    for (int t = 0; t < TT; t++) {
        const int cur = t & 1;
        const int nxt = cur ^ 1;

        // ---- fill Is[k][bb] = h_{t-1} ----
        {
            const float* hrow = g_h[cur] + (size_t)(b0 + fb) * HH + fq * 32;
            #pragma unroll
            for (int kk = 0; kk < 32; kk += 4) {
                float4 v = __ldcg((const float4*)(hrow + kk));
                int kb = fq * 32 + kk;
                Is[(kb + 0) * 32 + fb] = v.x;
                Is[(kb + 1) * 32 + fb] = v.y;
                Is[(kb + 2) * 32 + fb] = v.z;
                Is[(kb + 3) * 32 + fb] = v.w;
            }
        }
        // ---- stage xg_t slice ----
        {
            #pragma unroll
            for (int i = 0; i < 2; i++) {
                int idx = tid + i * 256;
                int c  = idx & 15, bb = idx >> 4;
                int g  = c >> 2,  u4 = (c & 3) * 4;
                const float* src = g_xg + (size_t)(t * BB + b0 + bb) * G4
                                        + g * HH + hu0 + u4;
                float4 v = __ldcg((const float4*)src);
                int row = g * 16 + u4;
                xg_s[(row + 0) * 33 + bb] = v.x;
                xg_s[(row + 1) * 33 + bb] = v.y;
                xg_s[(row + 2) * 33 + bb] = v.z;
                xg_s[(row + 3) * 33 + bb] = v.w;
            }
        }
        __syncthreads();

        // ---- GEMM: partial gates = Whh-slice . h ----
        {
            unsigned long long acc[4][2];
            #pragma unroll
            for (int r = 0; r < 4; r++) { acc[r][0] = 0ull; acc[r][1] = 0ull; }
            const float* wp = Ws + (kh * 128) * 64 + rr0;
            const float* ip = Is + (kh * 128) * 32 + bq0;
            #pragma unroll 8
            for (int k = 0; k < 128; k++) {
                float4 w = *(const float4*)wp;
                ulonglong2 vv = *(const ulonglong2*)ip;
                unsigned long long w0 = pack2(w.x), w1 = pack2(w.y);
                unsigned long long w2 = pack2(w.z), w3 = pack2(w.w);
                fma2(acc[0][0], w0, vv.x); fma2(acc[0][1], w0, vv.y);
                fma2(acc[1][0], w1, vv.x); fma2(acc[1][1], w1, vv.y);
                fma2(acc[2][0], w2, vv.x); fma2(acc[2][1], w2, vv.y);
                fma2(acc[3][0], w3, vv.x); fma2(acc[3][1], w3, vv.y);
                wp += 64; ip += 32;
            }
            #pragma unroll
            for (int r = 0; r < 4; r++) {
                int row = kh * 64 + rr0 + r;
                #pragma unroll
                for (int p = 0; p < 2; p++) {
                    union { unsigned long long u; float2 f; } cv; cv.u = acc[r][p];
                    gates[row * 33 + bq0 + 2 * p + 0] = cv.f.x;
                    gates[row * 33 + bq0 + 2 * p + 1] = cv.f.y;
                }
            }
        }
        __syncthreads();

        // ---- gates + state update ----
        #pragma unroll
        for (int j = 0; j < 2; j++) {
            int e  = tid + j * TPB;
            int uu = e >> 5, bb = e & 31;
            float gi = gates[(uu     ) * 33 + bb] + gates[(64 + uu     ) * 33 + bb] + xg_s[(uu     ) * 33 + bb];
            float gf = gates[(16 + uu) * 33 + bb] + gates[(64 + 16 + uu) * 33 + bb] + xg_s[(16 + uu) * 33 + bb];
            float gg = gates[(32 + uu) * 33 + bb] + gates[(64 + 32 + uu) * 33 + bb] + xg_s[(32 + uu) * 33 + bb];
            float go = gates[(48 + uu) * 33 + bb] + gates[(64 + 48 + uu) * 33 + bb] + xg_s[(48 + uu) * 33 + bb];
            float c  = c_s[e];
            c = sigmoidf_(gf) * c + sigmoidf_(gi) * tanhf_(gg);
            float h = sigmoidf_(go) * tanhf_(c);
            c_s[e] = c;
            size_t hidx = (size_t)(b0 + bb) * HH + hu0 + uu;
            g_h[nxt][hidx] = h;
            if (layer == 0) {
                g_h1[((size_t)(b0 + bb) * TT + t) * HH + hu0 + uu] = h;
            } else if (t == TT - 1) {
                g_last[hidx] = h;
            }
        }
        grid_barrier(++ep);
    }
}

// ======================= epilogue ===========================================
__global__ void __launch_bounds__(256)
epilogue_kernel(const float* __restrict__ W1, const float* __restrict__ b1,
                const float* __restrict__ W2, const float* __restrict__ b2,
                float* __restrict__ out)
{
    const int b    = blockIdx.x;
    const int tid  = threadIdx.x;
    const int lane = tid & 31;
    const int warp = tid >> 5;

    __shared__ float last_s[HH];
    __shared__ float y_s[5 * HH];

    last_s[tid] = g_last[(size_t)b * HH + tid];
    __syncthreads();

    for (int j = warp; j < 5 * HH; j += 8) {
        const float* wr = W1 + (size_t)j * HH;
        float acc = 0.0f;
        for (int k = lane; k < HH; k += 32) acc += wr[k] * last_s[k];
        #pragma unroll
        for (int o = 16; o; o >>= 1) acc += __shfl_down_sync(0xffffffffu, acc, o);
        if (lane == 0) y_s[j] = acc + b1[j];
    }
    __syncthreads();

    if (warp < 4) {
        const float* wr = W2 + (size_t)warp * (5 * HH);
        float acc = 0.0f;
        for (int j = lane; j < 5 * HH; j += 32) acc += wr[j] * y_s[j];
        #pragma unroll
        for (int o = 16; o; o >>= 1) acc += __shfl_down_sync(0xffffffffu, acc, o);
        if (lane == 0) out[b * 4 + warp] = acc + b2[warp];
    }
}

// ======================= launcher ===========================================
extern "C" void kernel_launch(void* const* d_in, const int* in_sizes, int n_in,
                              void* d_out, int out_size)
{
    const float* x    = (const float*)d_in[0];
    const float* Wih0 = (const float*)d_in[1];
    const float* Whh0 = (const float*)d_in[2];
    const float* bih0 = (const float*)d_in[3];
    const float* bhh0 = (const float*)d_in[4];
    const float* Wih1 = (const float*)d_in[5];
    const float* Whh1 = (const float*)d_in[6];
    const float* bih1 = (const float*)d_in[7];
    const float* bhh1 = (const float*)d_in[8];
    const float* W1   = (const float*)d_in[9];
    const float* b1   = (const float*)d_in[10];
    const float* W2   = (const float*)d_in[11];
    const float* b2   = (const float*)d_in[12];
    float* out = (float*)d_out;

    cudaFuncSetAttribute(lstm_layer_kernel,
                         cudaFuncAttributeMaxDynamicSharedMemorySize, SMEM_BYTES);

    const int gemm_grid = (BB * TT / 128) * 8;   // 8192

    // launches: 1 init, 2 gemm0, 3 lstm0, 4 init, 5 gemm1, 6 lstm1 (ncu target), 7 epilogue
    init_sync_kernel<<<1, 1>>>();
    gemm_xg_kernel<II, false><<<gemm_grid, 256>>>(x, Wih0, bih0, bhh0);
    lstm_layer_kernel<<<NCTA, TPB, SMEM_BYTES>>>(Whh0, 0);
    init_sync_kernel<<<1, 1>>>();
    gemm_xg_kernel<HH, true><<<gemm_grid, 256>>>(nullptr, Wih1, bih1, bhh1);
    lstm_layer_kernel<<<NCTA, TPB, SMEM_BYTES>>>(Whh1, 1);
    epilogue_kernel<<<BB, 256>>>(W1, b1, W2, b2, out);
}